// round 8
// baseline (speedup 1.0000x reference)
#include <cuda_runtime.h>
#include <cuda_bf16.h>

// GivensRotationPerHead: H=64 heads, DIM=128, R=8128 rotations (triu i-major order).
// Round 7 (resubmit after infra failure):
//   - givens main loop: 4-wide j processing (legal reorder) -> 4 independent
//     vj dependency chains instead of 1 serial chain (was 64 cy/j latency-bound).
//   - combine: 512 threads, K split 2x44 across thread groups (4 warps/SMSP),
//     smem partial reduction. Structural copy (H1 = diag(I40, M)) kept.

#define NHEADS 64
#define DIMN   128
#define NROT   8128
#define TPB    128

#define SPLIT_I   40
#define SPLIT_B   5
#define NB        16
#define R_SPLIT   4300
#define RANGE0    4300
#define RANGE1    3828
#define MAXRANGE  4300
#define MDIM      88        // DIMN - SPLIT_I

__device__ __forceinline__ int rbase(int i) { return i * 127 - (i * (i - 1)) / 2; }
__device__ __forceinline__ int blockbase8(int b) { return 988 * b - 32 * b * (b - 1); }

__device__ __forceinline__ void frot(float& vi, float& vj, float a, float b) {
    float ni = fmaf(a, vj, vi);
    vj = fmaf(b, vi, vj);
    vi = ni;
}

// 8 MB global scratch: halfQ[task][128][128], task = head*2 + half
__device__ float g_halfQ[2 * NHEADS * DIMN * DIMN];

#define OFF_T   MAXRANGE
#define OFF_FI  (2 * MAXRANGE)
#define OFF_FJ  (3 * MAXRANGE)
#define OFF_AB  (4 * MAXRANGE)
#define OFF_RS  (4 * MAXRANGE + 2 * MAXRANGE)
#define SM_FLOATS (OFF_RS + DIMN)     // 25928 floats = 103712 B

__global__ __launch_bounds__(TPB)
void givens_half_kernel(const float* __restrict__ thetas,
                        const int*   __restrict__ rot_i,
                        const int*   __restrict__ rot_j)
{
    extern __shared__ float sm[];
    float*  C  = sm;
    float*  T  = sm + OFF_T;
    float*  Fi = sm + OFF_FI;
    float*  Fj = sm + OFF_FJ;
    float*  Qs = sm;                         // aliases C/T/Fi after pass 3
    float2* AB = (float2*)(sm + OFF_AB);
    float*  rs = sm + OFF_RS;

    const int tid  = threadIdx.x;
    const int task = blockIdx.x;
    const int head = task >> 1;
    const int half = task & 1;

    const int r0    = half ? R_SPLIT : 0;
    const int range = half ? RANGE1 : RANGE0;
    const int b_lo  = half ? SPLIT_B : 0;
    const int b_hi  = half ? NB : SPLIT_B;
    const int ilo   = half ? SPLIT_I : 0;
    const int ihi   = half ? DIMN : SPLIT_I;

    const float* th = thetas + (size_t)head * NROT + r0;

    // ---- pass 1: cos / tan ----
    for (int rl = tid; rl < range; rl += TPB) {
        float s, c;
        __sincosf(th[rl], &s, &c);
        C[rl] = c;
        T[rl] = __fdividef(s, c);
    }
    __syncthreads();

    // ---- pass 2: per-row prefix products (row = tid) ----
    {
        const int m = tid;
        float f = 1.0f;
        int kend = m < ihi ? m : ihi;
        for (int k = ilo; k < kend; ++k) {
            int rl = rbase(k) + (m - k - 1) - r0;
            Fj[rl] = f;
            f *= C[rl];
        }
        if (m >= ilo && m < ihi) {
            int base = rbase(m) - r0;
            for (int j = m + 1; j < DIMN; ++j) {
                int rl = base + (j - m - 1);
                Fi[rl] = f;
                f *= C[rl];
            }
        }
        rs[m] = f;
    }
    __syncthreads();

    // ---- pass 3: alpha/beta into blocked AB table ----
    for (int rl = tid; rl < range; rl += TPB) {
        int r = r0 + rl;
        int i = rot_i[r];
        int j = rot_j[r];
        float t  = T[rl];
        float fi = Fi[rl];
        float fj = Fj[rl];
        float al =  t * __fdividef(fj, fi);
        float be = -t * __fdividef(fi, fj);
        int b  = i >> 3;
        int a  = i & 7;
        int i0 = b << 3;
        int bb = blockbase8(b) - r0;
        int pos;
        if (j < i0 + 8) {
            int jj = j - i0;
            pos = bb + a * 7 - (a * (a - 1)) / 2 + (jj - a - 1);
        } else {
            pos = bb + 28 + ((j - i0 - 8) << 3) + a;
        }
        AB[pos] = make_float2(al, be);
    }
    __syncthreads();

    // ---- init Q~ = I ----
    for (int idx = tid; idx < DIMN * DIMN; idx += TPB)
        Qs[idx] = ((idx >> 7) == (idx & 127)) ? 1.0f : 0.0f;
    __syncthreads();

    // ---- main loop: 8-row register blocks, 4 j-columns per iteration ----
    // half1 columns < 40 are exact identity; warp 0 (cols 0-31) skips entirely.
    if (!(half && tid < 32)) {
        const int t = tid;
        for (int b = b_lo; b < b_hi; ++b) {
            const int i0 = b << 3;
            const int bb = blockbase8(b) - r0;

            float v[8];
            #pragma unroll
            for (int a = 0; a < 8; ++a) v[a] = Qs[(i0 + a) * DIMN + t];

            // intra-block triangle (28 rotations, original order)
            {
                const float2* abt = AB + bb;
                int p = 0;
                #pragma unroll
                for (int a = 0; a < 7; ++a)
                    #pragma unroll
                    for (int jj = a + 1; jj < 8; ++jj) {
                        float2 ab = abt[p++];
                        frot(v[a], v[jj], ab.x, ab.y);
                    }
            }

            // j-sweep: 4 columns per iter (sweep length always divisible by 8).
            // Legal reorder: same-row rotations keep ascending j; same-j keep
            // ascending row; other pairs are row-disjoint.
            for (int j = i0 + 8; j < DIMN; j += 4) {
                // AB entries for these 4 j's: 16 float2 = 8 float4, laid out
                // [jj][a] (a fastest). float4 q = rows (2*a2, 2*a2+1) at jj.
                const float4* abj =
                    (const float4*)(AB + bb + 28 + ((j - i0 - 8) << 3));

                float vj0 = Qs[(j + 0) * DIMN + t];
                float vj1 = Qs[(j + 1) * DIMN + t];
                float vj2 = Qs[(j + 2) * DIMN + t];
                float vj3 = Qs[(j + 3) * DIMN + t];

                #pragma unroll
                for (int a2 = 0; a2 < 4; ++a2) {
                    float4 q0 = abj[0 * 4 + a2];
                    float4 q1 = abj[1 * 4 + a2];
                    float4 q2 = abj[2 * 4 + a2];
                    float4 q3 = abj[3 * 4 + a2];
                    frot(v[2 * a2],     vj0, q0.x, q0.y);
                    frot(v[2 * a2 + 1], vj0, q0.z, q0.w);
                    frot(v[2 * a2],     vj1, q1.x, q1.y);
                    frot(v[2 * a2 + 1], vj1, q1.z, q1.w);
                    frot(v[2 * a2],     vj2, q2.x, q2.y);
                    frot(v[2 * a2 + 1], vj2, q2.z, q2.w);
                    frot(v[2 * a2],     vj3, q3.x, q3.y);
                    frot(v[2 * a2 + 1], vj3, q3.z, q3.w);
                }

                Qs[(j + 0) * DIMN + t] = vj0;
                Qs[(j + 1) * DIMN + t] = vj1;
                Qs[(j + 2) * DIMN + t] = vj2;
                Qs[(j + 3) * DIMN + t] = vj3;
            }

            #pragma unroll
            for (int a = 0; a < 8; ++a) Qs[(i0 + a) * DIMN + t] = v[a];
        }
    }
    __syncthreads();

    // ---- write scaled half to global scratch ----
    float* o = g_halfQ + (size_t)task * DIMN * DIMN;
    for (int idx = tid; idx < DIMN * DIMN; idx += TPB)
        o[idx] = rs[idx >> 7] * Qs[idx];
}

// ============================================================================
// Structural combine:
//   out[0:40, :] = H0[0:40, :]                        (copy, rh=0 CTA)
//   out[40+mb : 40+mb+44, :] = M[mb:mb+44, :] @ H0[40:, :]   (mb = rh*44)
// 512 threads: two 256-thread groups each do half of K (44), partials reduced
// through smem. Per-thread tile 3x8 over 44 GEMM rows (sM padded to 48).
// ============================================================================
#define GTPB 512
// sB [88][128] + sM [48][88] + sP [44][128]
#define GSM_B  0
#define GSM_M  (MDIM * DIMN)
#define GSM_P  (MDIM * DIMN + 48 * MDIM)
#define GSM_FLOATS (MDIM * DIMN + 48 * MDIM + 44 * DIMN)   // 21120 fl = 84480 B

__global__ __launch_bounds__(GTPB)
void combine_kernel(float* __restrict__ out)
{
    extern __shared__ float gs[];
    float* sB = gs + GSM_B;      // H0 rows 40..127: [kb][c]
    float* sM = gs + GSM_M;      // M slice: [m][k], rows 44..47 zero
    float* sP = gs + GSM_P;      // partials from K-group 1

    const int tid  = threadIdx.x;
    const int head = blockIdx.x >> 1;
    const int rh   = blockIdx.x & 1;
    const int mb   = rh * 44;

    const float* A = g_halfQ + (size_t)(head * 2 + 0) * DIMN * DIMN;  // H0
    const float* B = g_halfQ + (size_t)(head * 2 + 1) * DIMN * DIMN;  // H1
    float*       O = out + (size_t)head * DIMN * DIMN;

    // sB: H0[40:128][:] = 2816 float4
    {
        const float4* src = (const float4*)(A + 40 * DIMN);
        for (int i = tid; i < MDIM * DIMN / 4; i += GTPB)
            ((float4*)sB)[i] = src[i];
    }
    // zero pad rows 44..47 of sM
    for (int i = tid; i < 4 * MDIM; i += GTPB)
        sM[44 * MDIM + i] = 0.0f;
    // sM rows 0..43: M[mb+m][k] = H1[(40+mb+m)][40+k], 22 float4 per row
    for (int i = tid; i < 44 * 22; i += GTPB) {
        int m = i / 22, k4 = i % 22;
        ((float4*)(sM + m * MDIM))[k4] =
            *(const float4*)(B + (size_t)(40 + mb + m) * DIMN + 40 + k4 * 4);
    }
    // rh=0 CTA also copies out rows 0..39 (exact)
    if (rh == 0) {
        const float4* src = (const float4*)A;
        float4* dst = (float4*)O;
        for (int i = tid; i < 40 * DIMN / 4; i += GTPB)
            dst[i] = src[i];
    }
    __syncthreads();

    // GEMM: 44 rows x 128 cols, K=88 split as 2x44 across thread groups.
    const int g    = tid >> 8;          // K-group 0/1
    const int tid2 = tid & 255;
    const int tx   = tid2 & 15;
    const int ty   = tid2 >> 4;
    const int c0   = tx << 3;
    const int m0   = ty * 3;
    const int kb   = g * 44;

    float acc[3][8];
    #pragma unroll
    for (int i = 0; i < 3; ++i)
        #pragma unroll
        for (int j = 0; j < 8; ++j) acc[i][j] = 0.0f;

    float a0 = sM[(m0 + 0) * MDIM + kb];
    float a1 = sM[(m0 + 1) * MDIM + kb];
    float a2 = sM[(m0 + 2) * MDIM + kb];
    float4 b0 = *(const float4*)&sB[kb * DIMN + c0];
    float4 b1 = *(const float4*)&sB[kb * DIMN + c0 + 4];

    #pragma unroll 2
    for (int kk = 0; kk < 44; ++kk) {
        int k  = kb + kk;
        int kn = (kk + 1 < 44) ? k + 1 : k;
        float na0 = sM[(m0 + 0) * MDIM + kn];
        float na1 = sM[(m0 + 1) * MDIM + kn];
        float na2 = sM[(m0 + 2) * MDIM + kn];
        float4 nb0 = *(const float4*)&sB[kn * DIMN + c0];
        float4 nb1 = *(const float4*)&sB[kn * DIMN + c0 + 4];

        acc[0][0] = fmaf(a0, b0.x, acc[0][0]);
        acc[0][1] = fmaf(a0, b0.y, acc[0][1]);
        acc[0][2] = fmaf(a0, b0.z, acc[0][2]);
        acc[0][3] = fmaf(a0, b0.w, acc[0][3]);
        acc[0][4] = fmaf(a0, b1.x, acc[0][4]);
        acc[0][5] = fmaf(a0, b1.y, acc[0][5]);
        acc[0][6] = fmaf(a0, b1.z, acc[0][6]);
        acc[0][7] = fmaf(a0, b1.w, acc[0][7]);

        acc[1][0] = fmaf(a1, b0.x, acc[1][0]);
        acc[1][1] = fmaf(a1, b0.y, acc[1][1]);
        acc[1][2] = fmaf(a1, b0.z, acc[1][2]);
        acc[1][3] = fmaf(a1, b0.w, acc[1][3]);
        acc[1][4] = fmaf(a1, b1.x, acc[1][4]);
        acc[1][5] = fmaf(a1, b1.y, acc[1][5]);
        acc[1][6] = fmaf(a1, b1.z, acc[1][6]);
        acc[1][7] = fmaf(a1, b1.w, acc[1][7]);

        acc[2][0] = fmaf(a2, b0.x, acc[2][0]);
        acc[2][1] = fmaf(a2, b0.y, acc[2][1]);
        acc[2][2] = fmaf(a2, b0.z, acc[2][2]);
        acc[2][3] = fmaf(a2, b0.w, acc[2][3]);
        acc[2][4] = fmaf(a2, b1.x, acc[2][4]);
        acc[2][5] = fmaf(a2, b1.y, acc[2][5]);
        acc[2][6] = fmaf(a2, b1.z, acc[2][6]);
        acc[2][7] = fmaf(a2, b1.w, acc[2][7]);

        a0 = na0; a1 = na1; a2 = na2;
        b0 = nb0; b1 = nb1;
    }

    // K-group 1 stores partials; group 0 adds and writes out.
    if (g == 1) {
        #pragma unroll
        for (int i = 0; i < 3; ++i) {
            int m = m0 + i;
            if (m < 44) {
                float* p = sP + m * DIMN + c0;
                *(float4*)p       = make_float4(acc[i][0], acc[i][1], acc[i][2], acc[i][3]);
                *(float4*)(p + 4) = make_float4(acc[i][4], acc[i][5], acc[i][6], acc[i][7]);
            }
        }
    }
    __syncthreads();
    if (g == 0) {
        const int rowbase = 40 + mb;
        #pragma unroll
        for (int i = 0; i < 3; ++i) {
            int m = m0 + i;
            if (m < 44) {
                const float* p = sP + m * DIMN + c0;
                float4 p0 = *(const float4*)p;
                float4 p1 = *(const float4*)(p + 4);
                float* o = O + (size_t)(rowbase + m) * DIMN + c0;
                *(float4*)o = make_float4(acc[i][0] + p0.x, acc[i][1] + p0.y,
                                          acc[i][2] + p0.z, acc[i][3] + p0.w);
                *(float4*)(o + 4) = make_float4(acc[i][4] + p1.x, acc[i][5] + p1.y,
                                                acc[i][6] + p1.z, acc[i][7] + p1.w);
            }
        }
    }
}

extern "C" void kernel_launch(void* const* d_in, const int* in_sizes, int n_in,
                              void* d_out, int out_size)
{
    const float* thetas = (const float*)d_in[0];
    const int*   ri     = (const int*)d_in[1];
    const int*   rj     = (const int*)d_in[2];
    float*       out    = (float*)d_out;

    const size_t smem1 = SM_FLOATS * sizeof(float);    // 103712 B
    const size_t smem2 = GSM_FLOATS * sizeof(float);   //  84480 B
    cudaFuncSetAttribute(givens_half_kernel,
                         cudaFuncAttributeMaxDynamicSharedMemorySize, (int)smem1);
    cudaFuncSetAttribute(combine_kernel,
                         cudaFuncAttributeMaxDynamicSharedMemorySize, (int)smem2);

    givens_half_kernel<<<2 * NHEADS, TPB, smem1>>>(thetas, ri, rj);
    combine_kernel<<<2 * NHEADS, GTPB, smem2>>>(out);
}